// round 2
// baseline (speedup 1.0000x reference)
#include <cuda_runtime.h>
#include <math.h>

// ---------------------------------------------------------------------------
// Problem constants
// ---------------------------------------------------------------------------
#define B_       32
#define Q_       300
#define C_       91
#define A_       10
#define TOPK_    50
#define NKEEP_   256
#define ML_      128          // MASK_LEN
#define LMAX_    23           // zigzag first 256 coeffs all have k,l <= 22
#define TOT_     (Q_ * C_)    // 27300
#define NCH_     8            // topk stage-A chunks per batch
#define CHUNK_   3413         // ceil(27300/8)

// Output layout (flattened tuple, f32)
#define OFF_S   ((size_t)0)
#define OFF_L   ((size_t)(B_ * TOPK_))                         // 1600
#define OFF_B   (OFF_L + (size_t)(B_ * TOPK_))                 // 3200
#define OFF_M   (OFF_B + (size_t)(B_ * TOPK_ * 4))             // 9600
#define OFF_SI  (OFF_M + (size_t)(B_ * TOPK_ * ML_ * ML_))     // 26224000
#define OFF_LI  (OFF_SI + (size_t)(B_ * TOPK_))                // 26225600
#define OFF_LA  (OFF_LI + (size_t)(B_ * TOPK_))                // 26227200

#define NEG_INF (-3.402823466e38f)

// ---------------------------------------------------------------------------
// Device scratch (no allocations allowed)
// ---------------------------------------------------------------------------
__device__ float g_D[LMAX_ * ML_];          // first 23 rows of the DCT matrix
__device__ int   g_cnt[LMAX_];              // per-l coefficient counts
__device__ int   g_pack[LMAX_ * LMAX_];     // (kc<<16)|coeff_index, grouped by l
__device__ float g_cand_v[B_ * NCH_ * TOPK_];
__device__ int   g_cand_i[B_ * NCH_ * TOPK_];
__device__ int   g_topq[B_ * TOPK_];        // final topk query indices

// ---------------------------------------------------------------------------
// Init kernel: DCT rows (double precision, matching numpy) + zigzag lists
// ---------------------------------------------------------------------------
__global__ void init_kernel() {
    int tid = threadIdx.x;
    const double s2n = sqrt(2.0 / (double)ML_);
    const double s05 = sqrt(0.5);
    for (int idx = tid; idx < LMAX_ * ML_; idx += blockDim.x) {
        int k = idx / ML_, m = idx % ML_;
        double v = cospi((2.0 * m + 1.0) * k / (2.0 * ML_)) * s2n;
        if (k == 0) v *= s05;
        g_D[idx] = (float)v;
    }
    if (tid == 0) {
        for (int l = 0; l < LMAX_; l++) g_cnt[l] = 0;
        int c = 0;
        for (int s = 0; s < 2 * ML_ - 1 && c < NKEEP_; s++) {
            if ((s & 1) == 0) {
                int rhi = s < ML_ - 1 ? s : ML_ - 1;
                int rlo = s - ML_ + 1 > 0 ? s - ML_ + 1 : 0;
                for (int r = rhi; r >= rlo && c < NKEEP_; r--) {
                    int kc = r, lc = s - r;
                    int j = g_cnt[lc]++;
                    g_pack[lc * LMAX_ + j] = (kc << 16) | c;
                    c++;
                }
            } else {
                int rlo = s - ML_ + 1 > 0 ? s - ML_ + 1 : 0;
                int rhi = s < ML_ - 1 ? s : ML_ - 1;
                for (int r = rlo; r <= rhi && c < NKEEP_; r++) {
                    int kc = r, lc = s - r;
                    int j = g_cnt[lc]++;
                    g_pack[lc * LMAX_ + j] = (kc << 16) | c;
                    c++;
                }
            }
        }
    }
}

// ---------------------------------------------------------------------------
// Top-k stage A: per-(batch,chunk) top-50 via 50 masked argmax passes in SMEM
// ---------------------------------------------------------------------------
__global__ void __launch_bounds__(256) topk_stageA(const float* __restrict__ logits) {
    int b  = blockIdx.x / NCH_;
    int ch = blockIdx.x % NCH_;
    int start = ch * CHUNK_;
    int len   = TOT_ - start < CHUNK_ ? TOT_ - start : CHUNK_;

    __shared__ float sv[CHUNK_];
    __shared__ float rv[256];
    __shared__ int   ri[256];

    const float* base = logits + (size_t)b * TOT_;
    for (int i = threadIdx.x; i < len; i += 256) sv[i] = base[start + i];
    __syncthreads();

    for (int r = 0; r < TOPK_; r++) {
        float bv = NEG_INF; int bi = 0x7fffffff;
        for (int i = threadIdx.x; i < len; i += 256) {
            float v = sv[i];
            if (v > bv || (v == bv && i < bi)) { bv = v; bi = i; }
        }
        rv[threadIdx.x] = bv; ri[threadIdx.x] = bi;
        __syncthreads();
        for (int o = 128; o > 0; o >>= 1) {
            if (threadIdx.x < o) {
                float v2 = rv[threadIdx.x + o]; int i2 = ri[threadIdx.x + o];
                if (v2 > rv[threadIdx.x] ||
                    (v2 == rv[threadIdx.x] && i2 < ri[threadIdx.x])) {
                    rv[threadIdx.x] = v2; ri[threadIdx.x] = i2;
                }
            }
            __syncthreads();
        }
        if (threadIdx.x == 0) {
            int o = (b * NCH_ + ch) * TOPK_ + r;
            g_cand_v[o] = rv[0];
            g_cand_i[o] = start + ri[0];
            sv[ri[0]] = NEG_INF;
        }
        __syncthreads();
    }
}

// ---------------------------------------------------------------------------
// Top-k stage B: merge 400 candidates/batch, write all small outputs
// ---------------------------------------------------------------------------
__global__ void __launch_bounds__(256) topk_stageB(
    const float* __restrict__ bbox, const float* __restrict__ interms,
    const float* __restrict__ actions, const int* __restrict__ tsz,
    float* __restrict__ out)
{
    int b = blockIdx.x, tid = threadIdx.x;
    const int NC = NCH_ * TOPK_;  // 400

    __shared__ float cv[NC];
    __shared__ int   ci[NC];
    __shared__ float rv[256];
    __shared__ int   ri[256];
    __shared__ int   rs[256];
    __shared__ float sel_v[TOPK_];
    __shared__ int   sel_i[TOPK_];

    for (int i = tid; i < NC; i += 256) {
        cv[i] = g_cand_v[b * NC + i];
        ci[i] = g_cand_i[b * NC + i];
    }
    __syncthreads();

    for (int r = 0; r < TOPK_; r++) {
        float bv = NEG_INF; int bgi = 0x7fffffff; int bslot = -1;
        for (int i = tid; i < NC; i += 256) {
            float v = cv[i]; int gi = ci[i];
            if (v > bv || (v == bv && gi < bgi)) { bv = v; bgi = gi; bslot = i; }
        }
        rv[tid] = bv; ri[tid] = bgi; rs[tid] = bslot;
        __syncthreads();
        for (int o = 128; o > 0; o >>= 1) {
            if (tid < o) {
                float v2 = rv[tid + o]; int i2 = ri[tid + o];
                if (v2 > rv[tid] || (v2 == rv[tid] && i2 < ri[tid])) {
                    rv[tid] = v2; ri[tid] = i2; rs[tid] = rs[tid + o];
                }
            }
            __syncthreads();
        }
        if (tid == 0) {
            sel_v[r] = rv[0];
            sel_i[r] = ri[0];
            cv[rs[0]] = NEG_INF;
        }
        __syncthreads();
    }

    if (tid < TOPK_) {
        int r = tid;
        float val = sel_v[r];
        int   gi  = sel_i[r];
        int   q   = gi / C_;
        int   lab = gi - q * C_;
        g_topq[b * TOPK_ + r] = q;

        out[OFF_S + b * TOPK_ + r] = 1.0f / (1.0f + expf(-val));
        out[OFF_L + b * TOPK_ + r] = (float)lab;

        const float* bb = bbox + ((size_t)b * Q_ + q) * 4;
        float cx = bb[0], cy = bb[1], w = bb[2], h = bb[3];
        float ih = (float)tsz[b * 2 + 0];
        float iw = (float)tsz[b * 2 + 1];
        float* ob = out + OFF_B + ((size_t)b * TOPK_ + r) * 4;
        ob[0] = (cx - 0.5f * w) * iw;
        ob[1] = (cy - 0.5f * h) * ih;
        ob[2] = (cx + 0.5f * w) * iw;
        ob[3] = (cy + 0.5f * h) * ih;

        const float* it = interms + ((size_t)b * Q_ + q) * C_;
        float m = it[0]; int am = 0;
        for (int c = 1; c < C_; c++) {
            float v = it[c];
            if (v > m) { m = v; am = c; }
        }
        out[OFF_SI + b * TOPK_ + r] = 1.0f / (1.0f + expf(-m));
        out[OFF_LI + b * TOPK_ + r] = (float)am;
    }
    if (tid == 0) {
        const float* ac = actions + (size_t)b * A_;
        float m = ac[0]; int am = 0;
        for (int a = 1; a < A_; a++)
            if (ac[a] > m) { m = ac[a]; am = a; }
        out[OFF_LA + b] = (float)am;
    }
}

// ---------------------------------------------------------------------------
// Masks kernel: one CTA per (b, rank) tile.
// Sparse inverse-DCT: T[l][n] = sum_k D[k][n]*v_zz, then M = T^T-contract D,
// all M values held in registers; block max/min reduce; threshold; write.
// ---------------------------------------------------------------------------
__global__ void __launch_bounds__(256) masks_kernel(
    const float* __restrict__ vec, float* __restrict__ out)
{
    __shared__ float sD[LMAX_ * ML_];     // 11.75 KB
    __shared__ float sT[LMAX_ * ML_];     // 11.75 KB
    __shared__ float sv[NKEEP_];          // 1 KB
    __shared__ int   spack[LMAX_ * LMAX_];
    __shared__ int   scnt[LMAX_];
    __shared__ float red[17];

    int tid  = threadIdx.x;
    int tile = blockIdx.x;
    int b    = tile / TOPK_;
    int q    = g_topq[tile];

    sv[tid] = vec[((size_t)b * Q_ + q) * NKEEP_ + tid];
    for (int i = tid; i < LMAX_ * ML_; i += 256) sD[i] = g_D[i];
    for (int i = tid; i < LMAX_ * LMAX_; i += 256) spack[i] = g_pack[i];
    if (tid < LMAX_) scnt[tid] = g_cnt[tid];
    __syncthreads();

    // T[l][n]
    for (int idx = tid; idx < LMAX_ * ML_; idx += 256) {
        int l = idx >> 7, n = idx & 127;
        float acc = 0.0f;
        int cnt = scnt[l];
        for (int j = 0; j < cnt; j++) {
            int pk = spack[l * LMAX_ + j];
            int kc = pk >> 16, c = pk & 0xffff;
            acc = fmaf(sv[c], sD[kc * ML_ + n], acc);
        }
        sT[idx] = acc;
    }
    __syncthreads();

    // M[n][m] in registers: each thread owns row n = tid>>1, half mb = (tid&1)*64
    int n  = tid >> 1;
    int mb = (tid & 1) << 6;
    float acc[64];
    #pragma unroll
    for (int j = 0; j < 64; j++) acc[j] = 0.0f;

    for (int l = 0; l < LMAX_; l++) {
        float tl = sT[l * ML_ + n];
        const float* dr = &sD[l * ML_ + mb];
        #pragma unroll
        for (int j = 0; j < 64; j++) acc[j] = fmaf(tl, dr[j], acc[j]);
    }

    // block max/min
    float mx = acc[0], mn = acc[0];
    #pragma unroll
    for (int j = 1; j < 64; j++) { mx = fmaxf(mx, acc[j]); mn = fminf(mn, acc[j]); }
    for (int o = 16; o; o >>= 1) {
        mx = fmaxf(mx, __shfl_xor_sync(0xffffffffu, mx, o));
        mn = fminf(mn, __shfl_xor_sync(0xffffffffu, mn, o));
    }
    if ((tid & 31) == 0) { red[tid >> 5] = mx; red[8 + (tid >> 5)] = mn; }
    __syncthreads();
    if (tid == 0) {
        float MX = red[0], MN = red[8];
        for (int w = 1; w < 8; w++) { MX = fmaxf(MX, red[w]); MN = fminf(MN, red[8 + w]); }
        red[16] = 0.5f * (MX + MN);
    }
    __syncthreads();
    float th = red[16];

    float* ob = out + OFF_M + (size_t)tile * (ML_ * ML_) + n * ML_ + mb;
    #pragma unroll
    for (int j = 0; j < 64; j += 4) {
        float4 w4;
        w4.x = acc[j]     > th ? 1.0f : 0.0f;
        w4.y = acc[j + 1] > th ? 1.0f : 0.0f;
        w4.z = acc[j + 2] > th ? 1.0f : 0.0f;
        w4.w = acc[j + 3] > th ? 1.0f : 0.0f;
        *reinterpret_cast<float4*>(ob + j) = w4;
    }
}

// ---------------------------------------------------------------------------
// Launch
// ---------------------------------------------------------------------------
extern "C" void kernel_launch(void* const* d_in, const int* in_sizes, int n_in,
                              void* d_out, int out_size)
{
    const float* logits  = (const float*)d_in[0];
    const float* bbox    = (const float*)d_in[1];
    const float* vec     = (const float*)d_in[2];
    const float* interms = (const float*)d_in[3];
    const float* actions = (const float*)d_in[4];
    const int*   tsz     = (const int*)d_in[5];
    float* out = (float*)d_out;

    init_kernel<<<1, 256>>>();
    topk_stageA<<<B_ * NCH_, 256>>>(logits);
    topk_stageB<<<B_, 256>>>(bbox, interms, actions, tsz, out);
    masks_kernel<<<B_ * TOPK_, 256>>>(vec, out);
}

// round 3
// speedup vs baseline: 1.5846x; 1.5846x over previous
#include <cuda_runtime.h>
#include <math.h>

// ---------------------------------------------------------------------------
// Problem constants
// ---------------------------------------------------------------------------
#define B_       32
#define Q_       300
#define C_       91
#define A_       10
#define TOPK_    50
#define NKEEP_   256
#define ML_      128          // MASK_LEN
#define LMAX_    23           // zigzag first 256 coeffs all have k,l <= 22
#define TOT_     (Q_ * C_)    // 27300

// Output layout (flattened tuple, f32)
#define OFF_S   ((size_t)0)
#define OFF_L   ((size_t)(B_ * TOPK_))                         // 1600
#define OFF_B   (OFF_L + (size_t)(B_ * TOPK_))                 // 3200
#define OFF_M   (OFF_B + (size_t)(B_ * TOPK_ * 4))             // 9600
#define OFF_SI  (OFF_M + (size_t)(B_ * TOPK_ * ML_ * ML_))     // 26224000
#define OFF_LI  (OFF_SI + (size_t)(B_ * TOPK_))                // 26225600
#define OFF_LA  (OFF_LI + (size_t)(B_ * TOPK_))                // 26227200

// ---------------------------------------------------------------------------
// Device scratch (no allocations allowed)
// ---------------------------------------------------------------------------
__device__ float g_D[LMAX_ * ML_];          // first 23 rows of the DCT matrix
__device__ int   g_cnt[LMAX_];              // per-l coefficient counts
__device__ int   g_pack[LMAX_ * LMAX_];     // (kc<<16)|coeff_index, grouped by l
__device__ int   g_topq[B_ * TOPK_];        // final topk query indices

// ---------------------------------------------------------------------------
// Init kernel: DCT rows (double precision, matching numpy) + zigzag lists
// ---------------------------------------------------------------------------
__global__ void init_kernel() {
    int tid = threadIdx.x;
    const double s2n = sqrt(2.0 / (double)ML_);
    const double s05 = sqrt(0.5);
    for (int idx = tid; idx < LMAX_ * ML_; idx += blockDim.x) {
        int k = idx / ML_, m = idx % ML_;
        double v = cospi((2.0 * m + 1.0) * k / (2.0 * ML_)) * s2n;
        if (k == 0) v *= s05;
        g_D[idx] = (float)v;
    }
    if (tid == 0) {
        for (int l = 0; l < LMAX_; l++) g_cnt[l] = 0;
        int c = 0;
        for (int s = 0; s < 2 * ML_ - 1 && c < NKEEP_; s++) {
            if ((s & 1) == 0) {
                int rhi = s < ML_ - 1 ? s : ML_ - 1;
                int rlo = s - ML_ + 1 > 0 ? s - ML_ + 1 : 0;
                for (int r = rhi; r >= rlo && c < NKEEP_; r--) {
                    int kc = r, lc = s - r;
                    int j = g_cnt[lc]++;
                    g_pack[lc * LMAX_ + j] = (kc << 16) | c;
                    c++;
                }
            } else {
                int rlo = s - ML_ + 1 > 0 ? s - ML_ + 1 : 0;
                int rhi = s < ML_ - 1 ? s : ML_ - 1;
                for (int r = rlo; r <= rhi && c < NKEEP_; r++) {
                    int kc = r, lc = s - r;
                    int j = g_cnt[lc]++;
                    g_pack[lc * LMAX_ + j] = (kc << 16) | c;
                    c++;
                }
            }
        }
    }
}

// ---------------------------------------------------------------------------
// Monotonic float->uint mapping (larger float => larger uint)
// ---------------------------------------------------------------------------
__device__ __forceinline__ unsigned mono(float f) {
    unsigned b = __float_as_uint(f);
    return (b & 0x80000000u) ? ~b : (b | 0x80000000u);
}

// ---------------------------------------------------------------------------
// Single-kernel exact top-50 via 4-level 8-bit radix select (1 CTA per batch)
// + full small-output epilogue (scores, labels, boxes, interms, actions)
// ---------------------------------------------------------------------------
__global__ void __launch_bounds__(1024) topk_kernel(
    const float* __restrict__ logits, const float* __restrict__ bbox,
    const float* __restrict__ interms, const float* __restrict__ actions,
    const int* __restrict__ tsz, float* __restrict__ out)
{
    int b   = blockIdx.x;
    int tid = threadIdx.x;
    const float* base = logits + (size_t)b * TOT_;

    __shared__ unsigned hist[256];
    __shared__ unsigned s_prefix;
    __shared__ int      s_krem;
    __shared__ int      s_cntgt;
    __shared__ unsigned sel_u[TOPK_];
    __shared__ int      sel_idx[TOPK_];
    __shared__ float    fin_v[TOPK_];
    __shared__ int      fin_i[TOPK_];
    __shared__ int      eqcnt[1024];

    if (tid == 0) { s_prefix = 0; s_krem = TOPK_; s_cntgt = 0; }

    // ---- 4 radix levels: find exact mono-value of the 50th largest ----
    for (int lev = 0; lev < 4; lev++) {
        int shift = 24 - 8 * lev;
        if (tid < 256) hist[tid] = 0;
        __syncthreads();
        unsigned pref    = s_prefix;
        unsigned hi_mask = (lev == 0) ? 0u : (0xffffffffu << (shift + 8));
        for (int i = tid; i < TOT_; i += 1024) {
            unsigned u = mono(__ldg(base + i));
            if ((u & hi_mask) == (pref & hi_mask))
                atomicAdd(&hist[(u >> shift) & 0xff], 1u);
        }
        __syncthreads();
        if (tid == 0) {
            int krem = s_krem;
            unsigned cum = 0;
            int bin;
            for (bin = 255; bin >= 0; bin--) {
                unsigned c = hist[bin];
                if (cum + c >= (unsigned)krem) break;
                cum += c;
            }
            s_krem   = krem - (int)cum;
            s_prefix = pref | ((unsigned)bin << shift);
        }
        __syncthreads();
    }

    unsigned uthr    = s_prefix;
    int      need_eq = s_krem;          // slots filled by u == uthr (index order)
    int      cnt_gt  = TOPK_ - need_eq; // count of u > uthr

    // ---- gather: contiguous per-thread blocks (index-ordered for ties) ----
    const int BLK = (TOT_ + 1023) / 1024;  // 27
    int lo = tid * BLK;
    int hi = lo + BLK < TOT_ ? lo + BLK : TOT_;
    int myeq = 0;
    for (int i = lo; i < hi; i++) {
        unsigned u = mono(__ldg(base + i));
        if (u > uthr) {
            int s = atomicAdd(&s_cntgt, 1);
            sel_u[s] = u; sel_idx[s] = i;
        } else if (u == uthr) myeq++;
    }
    eqcnt[tid] = myeq;
    __syncthreads();
    // inclusive scan over 1024 thread counts
    for (int o = 1; o < 1024; o <<= 1) {
        int v = 0;
        if (tid >= o) v = eqcnt[tid - o];
        __syncthreads();
        eqcnt[tid] += v;
        __syncthreads();
    }
    int pos = eqcnt[tid] - myeq;  // exclusive prefix
    if (myeq > 0 && pos < need_eq) {
        int p = pos;
        for (int i = lo; i < hi && p < need_eq; i++) {
            unsigned u = mono(__ldg(base + i));
            if (u == uthr) { sel_u[cnt_gt + p] = u; sel_idx[cnt_gt + p] = i; p++; }
        }
    }
    __syncthreads();

    // ---- O(50^2) rank sort: (value desc, index asc) ----
    if (tid < TOPK_) {
        unsigned ui = sel_u[tid]; int ii = sel_idx[tid];
        int r = 0;
        for (int j = 0; j < TOPK_; j++) {
            unsigned uj = sel_u[j]; int ij = sel_idx[j];
            if (uj > ui || (uj == ui && ij < ii)) r++;
        }
        unsigned fb = (ui & 0x80000000u) ? (ui ^ 0x80000000u) : ~ui;
        fin_v[r] = __uint_as_float(fb);
        fin_i[r] = ii;
    }
    __syncthreads();

    // ---- epilogue: all small outputs ----
    if (tid < TOPK_) {
        int r   = tid;
        float val = fin_v[r];
        int   gi  = fin_i[r];
        int   q   = gi / C_;
        int   lab = gi - q * C_;
        g_topq[b * TOPK_ + r] = q;

        out[OFF_S + b * TOPK_ + r] = 1.0f / (1.0f + expf(-val));
        out[OFF_L + b * TOPK_ + r] = (float)lab;

        const float* bb = bbox + ((size_t)b * Q_ + q) * 4;
        float cx = bb[0], cy = bb[1], w = bb[2], h = bb[3];
        float ihh = (float)tsz[b * 2 + 0];
        float iww = (float)tsz[b * 2 + 1];
        float* ob = out + OFF_B + ((size_t)b * TOPK_ + r) * 4;
        ob[0] = (cx - 0.5f * w) * iww;
        ob[1] = (cy - 0.5f * h) * ihh;
        ob[2] = (cx + 0.5f * w) * iww;
        ob[3] = (cy + 0.5f * h) * ihh;

        const float* it = interms + ((size_t)b * Q_ + q) * C_;
        float m = it[0]; int am = 0;
        for (int c = 1; c < C_; c++) {
            float v = it[c];
            if (v > m) { m = v; am = c; }
        }
        out[OFF_SI + b * TOPK_ + r] = 1.0f / (1.0f + expf(-m));
        out[OFF_LI + b * TOPK_ + r] = (float)am;
    }
    if (tid == 0) {
        const float* ac = actions + (size_t)b * A_;
        float m = ac[0]; int am = 0;
        for (int a = 1; a < A_; a++)
            if (ac[a] > m) { m = ac[a]; am = a; }
        out[OFF_LA + b] = (float)am;
    }
}

// ---------------------------------------------------------------------------
// Masks kernel: one CTA per (b, rank) tile.
// Sparse inverse-DCT: T[l][n] = sum_k D[k][n]*v_zz, then register-blocked
// outer product M[n][m] = sum_l T[l][n]*D[l][m]  (4n x 16m tile per thread,
// vector LDS: 5 x LDS.128 per l feeding 64 FMAs).
// ---------------------------------------------------------------------------
__global__ void __launch_bounds__(256) masks_kernel(
    const float* __restrict__ vec, float* __restrict__ out)
{
    __shared__ float sD[LMAX_ * ML_];     // 11.75 KB
    __shared__ float sT[LMAX_ * ML_];     // 11.75 KB
    __shared__ float sv[NKEEP_];          // 1 KB
    __shared__ int   spack[LMAX_ * LMAX_];
    __shared__ int   scnt[LMAX_];
    __shared__ float red[17];

    int tid  = threadIdx.x;
    int tile = blockIdx.x;
    int b    = tile / TOPK_;
    int q    = g_topq[tile];

    sv[tid] = vec[((size_t)b * Q_ + q) * NKEEP_ + tid];
    for (int i = tid; i < LMAX_ * ML_; i += 256) sD[i] = g_D[i];
    for (int i = tid; i < LMAX_ * LMAX_; i += 256) spack[i] = g_pack[i];
    if (tid < LMAX_) scnt[tid] = g_cnt[tid];
    __syncthreads();

    // T[l][n] (sparse: only coeffs with this l contribute)
    for (int idx = tid; idx < LMAX_ * ML_; idx += 256) {
        int l = idx >> 7, n = idx & 127;
        float acc = 0.0f;
        int cnt = scnt[l];
        for (int j = 0; j < cnt; j++) {
            int pk = spack[l * LMAX_ + j];
            int kc = pk >> 16, c = pk & 0xffff;
            acc = fmaf(sv[c], sD[kc * ML_ + n], acc);
        }
        sT[idx] = acc;
    }
    __syncthreads();

    // Register-blocked: thread owns rows n0..n0+3, cols m0..m0+15
    int n0 = (tid >> 3) << 2;        // 0,4,...,124
    int m0 = (tid & 7) << 4;         // 0,16,...,112

    float acc[4][16];
    #pragma unroll
    for (int i = 0; i < 4; i++)
        #pragma unroll
        for (int j = 0; j < 16; j++) acc[i][j] = 0.0f;

    #pragma unroll 1
    for (int l = 0; l < LMAX_; l++) {
        float4 tv = *reinterpret_cast<const float4*>(&sT[l * ML_ + n0]);
        float4 d0 = *reinterpret_cast<const float4*>(&sD[l * ML_ + m0]);
        float4 d1 = *reinterpret_cast<const float4*>(&sD[l * ML_ + m0 + 4]);
        float4 d2 = *reinterpret_cast<const float4*>(&sD[l * ML_ + m0 + 8]);
        float4 d3 = *reinterpret_cast<const float4*>(&sD[l * ML_ + m0 + 12]);
        float dv[16] = {d0.x,d0.y,d0.z,d0.w, d1.x,d1.y,d1.z,d1.w,
                        d2.x,d2.y,d2.z,d2.w, d3.x,d3.y,d3.z,d3.w};
        float tvv[4] = {tv.x, tv.y, tv.z, tv.w};
        #pragma unroll
        for (int i = 0; i < 4; i++)
            #pragma unroll
            for (int j = 0; j < 16; j++)
                acc[i][j] = fmaf(tvv[i], dv[j], acc[i][j]);
    }

    // block max/min
    float mx = acc[0][0], mn = acc[0][0];
    #pragma unroll
    for (int i = 0; i < 4; i++)
        #pragma unroll
        for (int j = 0; j < 16; j++) {
            mx = fmaxf(mx, acc[i][j]); mn = fminf(mn, acc[i][j]);
        }
    for (int o = 16; o; o >>= 1) {
        mx = fmaxf(mx, __shfl_xor_sync(0xffffffffu, mx, o));
        mn = fminf(mn, __shfl_xor_sync(0xffffffffu, mn, o));
    }
    if ((tid & 31) == 0) { red[tid >> 5] = mx; red[8 + (tid >> 5)] = mn; }
    __syncthreads();
    if (tid == 0) {
        float MX = red[0], MN = red[8];
        for (int w = 1; w < 8; w++) { MX = fmaxf(MX, red[w]); MN = fminf(MN, red[8 + w]); }
        red[16] = 0.5f * (MX + MN);
    }
    __syncthreads();
    float th = red[16];

    float* ob = out + OFF_M + (size_t)tile * (ML_ * ML_);
    #pragma unroll
    for (int i = 0; i < 4; i++) {
        float* row = ob + (size_t)(n0 + i) * ML_ + m0;
        #pragma unroll
        for (int j = 0; j < 16; j += 4) {
            float4 w4;
            w4.x = acc[i][j]     > th ? 1.0f : 0.0f;
            w4.y = acc[i][j + 1] > th ? 1.0f : 0.0f;
            w4.z = acc[i][j + 2] > th ? 1.0f : 0.0f;
            w4.w = acc[i][j + 3] > th ? 1.0f : 0.0f;
            *reinterpret_cast<float4*>(row + j) = w4;
        }
    }
}

// ---------------------------------------------------------------------------
// Launch
// ---------------------------------------------------------------------------
extern "C" void kernel_launch(void* const* d_in, const int* in_sizes, int n_in,
                              void* d_out, int out_size)
{
    const float* logits  = (const float*)d_in[0];
    const float* bbox    = (const float*)d_in[1];
    const float* vec     = (const float*)d_in[2];
    const float* interms = (const float*)d_in[3];
    const float* actions = (const float*)d_in[4];
    const int*   tsz     = (const int*)d_in[5];
    float* out = (float*)d_out;

    init_kernel<<<1, 256>>>();
    topk_kernel<<<B_, 1024>>>(logits, bbox, interms, actions, tsz, out);
    masks_kernel<<<B_ * TOPK_, 256>>>(vec, out);
}

// round 4
// speedup vs baseline: 2.0778x; 1.3113x over previous
#include <cuda_runtime.h>
#include <math.h>

// ---------------------------------------------------------------------------
// Problem constants
// ---------------------------------------------------------------------------
#define B_       32
#define Q_       300
#define C_       91
#define A_       10
#define TOPK_    50
#define NKEEP_   256
#define ML_      128          // MASK_LEN
#define LMAX_    23           // zigzag first 256 coeffs all have k,l <= 22
#define TOT_     (Q_ * C_)    // 27300
#define CAP_EQ   5000
#define CAP_EX   512

// Output layout (flattened tuple, f32)
#define OFF_S   ((size_t)0)
#define OFF_L   ((size_t)(B_ * TOPK_))                         // 1600
#define OFF_B   (OFF_L + (size_t)(B_ * TOPK_))                 // 3200
#define OFF_M   (OFF_B + (size_t)(B_ * TOPK_ * 4))             // 9600
#define OFF_SI  (OFF_M + (size_t)(B_ * TOPK_ * ML_ * ML_))     // 26224000
#define OFF_LI  (OFF_SI + (size_t)(B_ * TOPK_))                // 26225600
#define OFF_LA  (OFF_LI + (size_t)(B_ * TOPK_))                // 26227200

// ---------------------------------------------------------------------------
// Device scratch (no allocations allowed)
// ---------------------------------------------------------------------------
__device__ float g_D[LMAX_ * ML_];          // first 23 rows of the DCT matrix
__device__ int   g_topq[B_ * TOPK_];        // final topk query indices

// Monotonic float->uint mapping (larger float => larger uint)
__device__ __forceinline__ unsigned mono(float f) {
    unsigned b = __float_as_uint(f);
    return (b & 0x80000000u) ? ~b : (b | 0x80000000u);
}

// Parallel suffix-scan bin selection over hist[0..255] (hist[256] must be 0).
// Destroys hist (turns it into inclusive suffix sums). Exactly one thread
// updates s_prefix / s_krem.
__device__ __forceinline__ void select_bin(unsigned* hist, int tid, int shift,
                                           unsigned* s_prefix, int* s_krem)
{
    for (int off = 1; off < 256; off <<= 1) {
        unsigned v = 0;
        if (tid < 256 && tid + off < 256) v = hist[tid + off];
        __syncthreads();
        if (tid < 256) hist[tid] += v;
        __syncthreads();
    }
    int krem = *s_krem;
    __syncthreads();
    if (tid < 256) {
        int sb  = (int)hist[tid];
        int sb1 = (tid == 255) ? 0 : (int)hist[tid + 1];
        if (sb >= krem && sb1 < krem) {
            *s_prefix |= ((unsigned)tid) << shift;
            *s_krem    = krem - sb1;
        }
    }
    __syncthreads();
}

// ---------------------------------------------------------------------------
// Top-50 via radix select with SMEM compaction + all small outputs.
// Also computes the DCT table slice for this CTA (feeds masks_kernel).
// ---------------------------------------------------------------------------
__global__ void __launch_bounds__(1024) topk_kernel(
    const float* __restrict__ logits, const float* __restrict__ bbox,
    const float* __restrict__ interms, const float* __restrict__ actions,
    const int* __restrict__ tsz, float* __restrict__ out)
{
    int b   = blockIdx.x;
    int tid = threadIdx.x;
    const float* base = logits + (size_t)b * TOT_;

    __shared__ unsigned hist[257];
    __shared__ unsigned eq_u[CAP_EQ];
    __shared__ int      eq_i[CAP_EQ];
    __shared__ int      eqex[CAP_EX];
    __shared__ unsigned sel_u[TOPK_];
    __shared__ int      sel_idx[TOPK_];
    __shared__ float    fin_v[TOPK_];
    __shared__ int      fin_i[TOPK_];
    __shared__ int      eqcnt[1024];     // gmem-fallback scan only
    __shared__ unsigned s_prefix;
    __shared__ int      s_krem, s_neq, s_cntgt, s_cnte;

    // ---- DCT table slice: 2944 entries / 32 CTAs = 92 each ----
    {
        const double s2n = sqrt(2.0 / (double)ML_);
        const double s05 = sqrt(0.5);
        int idx0 = b * 92;
        for (int j = tid; j < 92; j += 1024) {
            int idx = idx0 + j;
            int k = idx / ML_, m = idx % ML_;
            double v = cospi((2.0 * m + 1.0) * k / (2.0 * ML_)) * s2n;
            if (k == 0) v *= s05;
            g_D[idx] = (float)v;
        }
    }

    if (tid == 0) { s_prefix = 0; s_krem = TOPK_; s_neq = 0; s_cntgt = 0; s_cnte = 0; }
    if (tid < 257) hist[tid] = 0;
    __syncthreads();

    // ---- level 0: histogram of top bytes (full pass #1) ----
    for (int i = tid; i < TOT_; i += 1024)
        atomicAdd(&hist[mono(__ldg(base + i)) >> 24], 1u);
    __syncthreads();
    select_bin(hist, tid, 24, &s_prefix, &s_krem);

    // ---- compact candidates sharing top byte of pivot (full pass #2) ----
    unsigned bin0 = s_prefix >> 24;
    for (int i = tid; i < TOT_; i += 1024) {
        unsigned u = mono(__ldg(base + i));
        if ((u >> 24) == bin0) {
            int s = atomicAdd(&s_neq, 1);
            if (s < CAP_EQ) { eq_u[s] = u; eq_i[s] = i; }
        }
    }
    __syncthreads();
    bool ovf = (s_neq > CAP_EQ);
    int  neq = s_neq < CAP_EQ ? s_neq : CAP_EQ;

    // ---- levels 1..3: refine on SMEM list (or gmem if overflow) ----
    for (int lev = 1; lev < 4; lev++) {
        int shift = 24 - 8 * lev;
        if (tid < 257) hist[tid] = 0;
        __syncthreads();
        unsigned pref    = s_prefix;
        unsigned hi_mask = 0xffffffffu << (shift + 8);
        if (!ovf) {
            for (int i = tid; i < neq; i += 1024) {
                unsigned u = eq_u[i];
                if ((u & hi_mask) == (pref & hi_mask))
                    atomicAdd(&hist[(u >> shift) & 0xff], 1u);
            }
        } else {
            for (int i = tid; i < TOT_; i += 1024) {
                unsigned u = mono(__ldg(base + i));
                if ((u & hi_mask) == (pref & hi_mask))
                    atomicAdd(&hist[(u >> shift) & 0xff], 1u);
            }
        }
        __syncthreads();
        select_bin(hist, tid, shift, &s_prefix, &s_krem);
    }

    unsigned uthr    = s_prefix;
    int      need_eq = s_krem;          // slots filled by u == uthr (index order)
    int      cnt_gt  = TOPK_ - need_eq; // count of u > uthr (guaranteed < 50)

    // ---- gather strictly-greater (full pass #3) ----
    for (int i = tid; i < TOT_; i += 1024) {
        unsigned u = mono(__ldg(base + i));
        if (u > uthr) {
            int s = atomicAdd(&s_cntgt, 1);
            sel_u[s] = u; sel_idx[s] = i;
        }
    }

    // ---- equal-to-pivot fill, index-ascending ----
    bool fell_back = ovf;
    if (!ovf) {
        for (int i = tid; i < neq; i += 1024) {
            if (eq_u[i] == uthr) {
                int s = atomicAdd(&s_cnte, 1);
                if (s < CAP_EX) eqex[s] = eq_i[i];
            }
        }
        __syncthreads();
        if (s_cnte <= CAP_EX) {
            if (tid == 0) {
                int cnt = s_cnte, last = -1;
                for (int r = 0; r < need_eq; r++) {
                    int best = 0x7fffffff;
                    for (int j = 0; j < cnt; j++) {
                        int v = eqex[j];
                        if (v > last && v < best) best = v;
                    }
                    sel_u[cnt_gt + r]   = uthr;
                    sel_idx[cnt_gt + r] = best;
                    last = best;
                }
            }
        } else {
            fell_back = true;
        }
        __syncthreads();
    }
    if (fell_back) {
        // gmem index-ordered fill via per-thread contiguous blocks + scan
        const int BLK = (TOT_ + 1023) / 1024;
        int lo = tid * BLK;
        int hi = lo + BLK < TOT_ ? lo + BLK : TOT_;
        int myeq = 0;
        for (int i = lo; i < hi; i++)
            if (mono(__ldg(base + i)) == uthr) myeq++;
        eqcnt[tid] = myeq;
        __syncthreads();
        for (int o = 1; o < 1024; o <<= 1) {
            int v = 0;
            if (tid >= o) v = eqcnt[tid - o];
            __syncthreads();
            eqcnt[tid] += v;
            __syncthreads();
        }
        int pos = eqcnt[tid] - myeq;
        if (myeq > 0 && pos < need_eq) {
            int p = pos;
            for (int i = lo; i < hi && p < need_eq; i++) {
                if (mono(__ldg(base + i)) == uthr) {
                    sel_u[cnt_gt + p]   = uthr;
                    sel_idx[cnt_gt + p] = i;
                    p++;
                }
            }
        }
    }
    __syncthreads();

    // ---- O(50^2) rank sort: (value desc, index asc) ----
    if (tid < TOPK_) {
        unsigned ui = sel_u[tid]; int ii = sel_idx[tid];
        int r = 0;
        for (int j = 0; j < TOPK_; j++) {
            unsigned uj = sel_u[j]; int ij = sel_idx[j];
            if (uj > ui || (uj == ui && ij < ii)) r++;
        }
        unsigned fb = (ui & 0x80000000u) ? (ui ^ 0x80000000u) : ~ui;
        fin_v[r] = __uint_as_float(fb);
        fin_i[r] = ii;
    }
    __syncthreads();

    // ---- epilogue: all small outputs ----
    if (tid < TOPK_) {
        int r   = tid;
        float val = fin_v[r];
        int   gi  = fin_i[r];
        int   q   = gi / C_;
        int   lab = gi - q * C_;
        g_topq[b * TOPK_ + r] = q;

        out[OFF_S + b * TOPK_ + r] = 1.0f / (1.0f + expf(-val));
        out[OFF_L + b * TOPK_ + r] = (float)lab;

        const float* bb = bbox + ((size_t)b * Q_ + q) * 4;
        float cx = bb[0], cy = bb[1], w = bb[2], h = bb[3];
        float ihh = (float)tsz[b * 2 + 0];
        float iww = (float)tsz[b * 2 + 1];
        float* ob = out + OFF_B + ((size_t)b * TOPK_ + r) * 4;
        ob[0] = (cx - 0.5f * w) * iww;
        ob[1] = (cy - 0.5f * h) * ihh;
        ob[2] = (cx + 0.5f * w) * iww;
        ob[3] = (cy + 0.5f * h) * ihh;

        const float* it = interms + ((size_t)b * Q_ + q) * C_;
        float m = it[0]; int am = 0;
        for (int c = 1; c < C_; c++) {
            float v = it[c];
            if (v > m) { m = v; am = c; }
        }
        out[OFF_SI + b * TOPK_ + r] = 1.0f / (1.0f + expf(-m));
        out[OFF_LI + b * TOPK_ + r] = (float)am;
    }
    if (tid == 0) {
        const float* ac = actions + (size_t)b * A_;
        float m = ac[0]; int am = 0;
        for (int a = 1; a < A_; a++)
            if (ac[a] > m) { m = ac[a]; am = a; }
        out[OFF_LA + b] = (float)am;
    }
}

// ---------------------------------------------------------------------------
// Masks kernel: one CTA per (b, rank) tile.
// Sparse inverse-DCT with closed-form zigzag:
//   coefficient c on diagonal s has k = s-l, c = tri(s) + (s even ? l : s-l).
//   T[l][n] = sum_s sv[c(s,l)] * D[s-l][n], then register-blocked
//   M[n][m] = sum_l T[l][n]*D[l][m]  (4n x 16m tile per thread).
// ---------------------------------------------------------------------------
__global__ void __launch_bounds__(256) masks_kernel(
    const float* __restrict__ vec, float* __restrict__ out)
{
    __shared__ float sD[LMAX_ * ML_];     // 11.75 KB
    __shared__ float sT[LMAX_ * ML_];     // 11.75 KB
    __shared__ float sv[NKEEP_];          // 1 KB
    __shared__ float red[17];

    int tid  = threadIdx.x;
    int tile = blockIdx.x;
    int b    = tile / TOPK_;
    int q    = g_topq[tile];

    sv[tid] = vec[((size_t)b * Q_ + q) * NKEEP_ + tid];
    for (int i = tid; i < LMAX_ * ML_; i += 256) sD[i] = g_D[i];
    __syncthreads();

    // T[l][n]: one coefficient per diagonal s >= l (s=22 only if l<=2)
    for (int idx = tid; idx < LMAX_ * ML_; idx += 256) {
        int l = idx >> 7, n = idx & 127;
        float acc = 0.0f;
        int smax = (l <= 2) ? 23 : 22;
        int tri  = (l * (l + 1)) >> 1;
        for (int s = l; s < smax; s++) {
            int t = (s & 1) ? (s - l) : l;
            int c = tri + t;
            acc = fmaf(sv[c], sD[(s - l) * ML_ + n], acc);
            tri += s + 1;
        }
        sT[idx] = acc;
    }
    __syncthreads();

    // Register-blocked: thread owns rows n0..n0+3, cols m0..m0+15
    int n0 = (tid >> 3) << 2;        // 0,4,...,124
    int m0 = (tid & 7) << 4;         // 0,16,...,112

    float acc[4][16];
    #pragma unroll
    for (int i = 0; i < 4; i++)
        #pragma unroll
        for (int j = 0; j < 16; j++) acc[i][j] = 0.0f;

    #pragma unroll 1
    for (int l = 0; l < LMAX_; l++) {
        float4 tv = *reinterpret_cast<const float4*>(&sT[l * ML_ + n0]);
        float4 d0 = *reinterpret_cast<const float4*>(&sD[l * ML_ + m0]);
        float4 d1 = *reinterpret_cast<const float4*>(&sD[l * ML_ + m0 + 4]);
        float4 d2 = *reinterpret_cast<const float4*>(&sD[l * ML_ + m0 + 8]);
        float4 d3 = *reinterpret_cast<const float4*>(&sD[l * ML_ + m0 + 12]);
        float dv[16] = {d0.x,d0.y,d0.z,d0.w, d1.x,d1.y,d1.z,d1.w,
                        d2.x,d2.y,d2.z,d2.w, d3.x,d3.y,d3.z,d3.w};
        float tvv[4] = {tv.x, tv.y, tv.z, tv.w};
        #pragma unroll
        for (int i = 0; i < 4; i++)
            #pragma unroll
            for (int j = 0; j < 16; j++)
                acc[i][j] = fmaf(tvv[i], dv[j], acc[i][j]);
    }

    // block max/min
    float mx = acc[0][0], mn = acc[0][0];
    #pragma unroll
    for (int i = 0; i < 4; i++)
        #pragma unroll
        for (int j = 0; j < 16; j++) {
            mx = fmaxf(mx, acc[i][j]); mn = fminf(mn, acc[i][j]);
        }
    for (int o = 16; o; o >>= 1) {
        mx = fmaxf(mx, __shfl_xor_sync(0xffffffffu, mx, o));
        mn = fminf(mn, __shfl_xor_sync(0xffffffffu, mn, o));
    }
    if ((tid & 31) == 0) { red[tid >> 5] = mx; red[8 + (tid >> 5)] = mn; }
    __syncthreads();
    if (tid == 0) {
        float MX = red[0], MN = red[8];
        for (int w = 1; w < 8; w++) { MX = fmaxf(MX, red[w]); MN = fminf(MN, red[8 + w]); }
        red[16] = 0.5f * (MX + MN);
    }
    __syncthreads();
    float th = red[16];

    float* ob = out + OFF_M + (size_t)tile * (ML_ * ML_);
    #pragma unroll
    for (int i = 0; i < 4; i++) {
        float* row = ob + (size_t)(n0 + i) * ML_ + m0;
        #pragma unroll
        for (int j = 0; j < 16; j += 4) {
            float4 w4;
            w4.x = acc[i][j]     > th ? 1.0f : 0.0f;
            w4.y = acc[i][j + 1] > th ? 1.0f : 0.0f;
            w4.z = acc[i][j + 2] > th ? 1.0f : 0.0f;
            w4.w = acc[i][j + 3] > th ? 1.0f : 0.0f;
            *reinterpret_cast<float4*>(row + j) = w4;
        }
    }
}

// ---------------------------------------------------------------------------
// Launch
// ---------------------------------------------------------------------------
extern "C" void kernel_launch(void* const* d_in, const int* in_sizes, int n_in,
                              void* d_out, int out_size)
{
    const float* logits  = (const float*)d_in[0];
    const float* bbox    = (const float*)d_in[1];
    const float* vec     = (const float*)d_in[2];
    const float* interms = (const float*)d_in[3];
    const float* actions = (const float*)d_in[4];
    const int*   tsz     = (const int*)d_in[5];
    float* out = (float*)d_out;

    topk_kernel<<<B_, 1024>>>(logits, bbox, interms, actions, tsz, out);
    masks_kernel<<<B_ * TOPK_, 256>>>(vec, out);
}

// round 8
// speedup vs baseline: 3.3187x; 1.5972x over previous
#include <cuda_runtime.h>
#include <math.h>

// ---------------------------------------------------------------------------
// Problem constants
// ---------------------------------------------------------------------------
#define B_       32
#define Q_       300
#define C_       91
#define A_       10
#define TOPK_    50
#define NKEEP_   256
#define ML_      128          // MASK_LEN
#define LMAX_    23           // zigzag first 256 coeffs all have k,l <= 22
#define TOT_     (Q_ * C_)    // 27300
#define NPT_     27           // elements per thread in topk (1024 threads)
#define CAP_EQ   5000
#define CAP_EX   512

// Output layout (flattened tuple, f32)
#define OFF_S   ((size_t)0)
#define OFF_L   ((size_t)(B_ * TOPK_))                         // 1600
#define OFF_B   (OFF_L + (size_t)(B_ * TOPK_))                 // 3200
#define OFF_M   (OFF_B + (size_t)(B_ * TOPK_ * 4))             // 9600
#define OFF_SI  (OFF_M + (size_t)(B_ * TOPK_ * ML_ * ML_))     // 26224000
#define OFF_LI  (OFF_SI + (size_t)(B_ * TOPK_))                // 26225600
#define OFF_LA  (OFF_LI + (size_t)(B_ * TOPK_))                // 26227200

// ---------------------------------------------------------------------------
// Device scratch (no allocations allowed)
// ---------------------------------------------------------------------------
__device__ float g_D[LMAX_ * ML_];          // first 23 rows of the DCT matrix
__device__ int   g_topq[B_ * TOPK_];        // final topk query indices

// Monotonic float->uint mapping (larger float => larger uint)
__device__ __forceinline__ unsigned mono(float f) {
    unsigned b = __float_as_uint(f);
    return (b & 0x80000000u) ? ~b : (b | 0x80000000u);
}

// Parallel suffix-scan bin selection over hist[0..255] (hist[256] must be 0).
// Destroys hist. Exactly one thread updates s_prefix / s_krem.
__device__ __forceinline__ void select_bin(unsigned* hist, int tid, int shift,
                                           unsigned* s_prefix, int* s_krem)
{
    for (int off = 1; off < 256; off <<= 1) {
        unsigned v = 0;
        if (tid < 256 && tid + off < 256) v = hist[tid + off];
        __syncthreads();
        if (tid < 256) hist[tid] += v;
        __syncthreads();
    }
    int krem = *s_krem;
    __syncthreads();
    if (tid < 256) {
        int sb  = (int)hist[tid];
        int sb1 = (tid == 255) ? 0 : (int)hist[tid + 1];
        if (sb >= krem && sb1 < krem) {
            *s_prefix |= ((unsigned)tid) << shift;
            *s_krem    = krem - sb1;
        }
    }
    __syncthreads();
}

// ---------------------------------------------------------------------------
// Top-50 via radix select; values register-resident after one gmem pass.
// Also computes the DCT table slice for this CTA (feeds masks_kernel).
// ---------------------------------------------------------------------------
__global__ void __launch_bounds__(1024) topk_kernel(
    const float* __restrict__ logits, const float* __restrict__ bbox,
    const float* __restrict__ interms, const float* __restrict__ actions,
    const int* __restrict__ tsz, float* __restrict__ out)
{
    int b   = blockIdx.x;
    int tid = threadIdx.x;
    const float* base = logits + (size_t)b * TOT_;

    __shared__ unsigned hist[257];
    __shared__ unsigned eq_u[CAP_EQ];
    __shared__ int      eq_i[CAP_EQ];
    __shared__ int      eqex[CAP_EX];
    __shared__ unsigned sel_u[TOPK_];
    __shared__ int      sel_idx[TOPK_];
    __shared__ float    fin_v[TOPK_];
    __shared__ int      fin_i[TOPK_];
    __shared__ int      eqcnt[1024];     // gmem-fallback scan only
    __shared__ unsigned s_prefix;
    __shared__ int      s_krem, s_neq, s_cntgt, s_cnte;

    // ---- DCT table slice: 2944 entries / 32 CTAs = 92 each ----
    {
        const double s2n = sqrt(2.0 / (double)ML_);
        const double s05 = sqrt(0.5);
        int idx0 = b * 92;
        for (int j = tid; j < 92; j += 1024) {
            int idx = idx0 + j;
            int k = idx / ML_, m = idx % ML_;
            double v = cospi((2.0 * m + 1.0) * k / (2.0 * ML_)) * s2n;
            if (k == 0) v *= s05;
            g_D[idx] = (float)v;
        }
    }

    if (tid == 0) { s_prefix = 0; s_krem = TOPK_; s_neq = 0; s_cntgt = 0; s_cnte = 0; }
    if (tid < 257) hist[tid] = 0;
    __syncthreads();

    // ---- single gmem pass: load into registers + level-0 histogram ----
    unsigned uv[NPT_];
    #pragma unroll
    for (int p = 0; p < NPT_; p++) {
        int i = tid + p * 1024;
        unsigned u = 0;                   // mono(-inf)-ish: never selected
        if (i < TOT_) u = mono(__ldg(base + i));
        uv[p] = u;
        if (i < TOT_) atomicAdd(&hist[u >> 24], 1u);
    }
    __syncthreads();
    select_bin(hist, tid, 24, &s_prefix, &s_krem);

    // ---- compact candidates sharing top byte of pivot (registers) ----
    unsigned bin0 = s_prefix >> 24;
    #pragma unroll
    for (int p = 0; p < NPT_; p++) {
        int i = tid + p * 1024;
        if (i < TOT_ && (uv[p] >> 24) == bin0) {
            int s = atomicAdd(&s_neq, 1);
            if (s < CAP_EQ) { eq_u[s] = uv[p]; eq_i[s] = i; }
        }
    }
    __syncthreads();
    bool ovf = (s_neq > CAP_EQ);
    int  neq = s_neq < CAP_EQ ? s_neq : CAP_EQ;

    // ---- levels 1..3: refine on SMEM list (or registers if overflow) ----
    for (int lev = 1; lev < 4; lev++) {
        int shift = 24 - 8 * lev;
        if (tid < 257) hist[tid] = 0;
        __syncthreads();
        unsigned pref    = s_prefix;
        unsigned hi_mask = 0xffffffffu << (shift + 8);
        if (!ovf) {
            for (int i = tid; i < neq; i += 1024) {
                unsigned u = eq_u[i];
                if ((u & hi_mask) == (pref & hi_mask))
                    atomicAdd(&hist[(u >> shift) & 0xff], 1u);
            }
        } else {
            #pragma unroll
            for (int p = 0; p < NPT_; p++) {
                int i = tid + p * 1024;
                unsigned u = uv[p];
                if (i < TOT_ && (u & hi_mask) == (pref & hi_mask))
                    atomicAdd(&hist[(u >> shift) & 0xff], 1u);
            }
        }
        __syncthreads();
        select_bin(hist, tid, shift, &s_prefix, &s_krem);
    }

    unsigned uthr    = s_prefix;
    int      need_eq = s_krem;          // slots filled by u == uthr (index order)
    int      cnt_gt  = TOPK_ - need_eq; // count of u > uthr (guaranteed < 50)

    // ---- gather strictly-greater (registers) ----
    #pragma unroll
    for (int p = 0; p < NPT_; p++) {
        int i = tid + p * 1024;
        if (i < TOT_ && uv[p] > uthr) {
            int s = atomicAdd(&s_cntgt, 1);
            sel_u[s] = uv[p]; sel_idx[s] = i;
        }
    }

    // ---- equal-to-pivot fill, index-ascending ----
    bool fell_back = ovf;
    if (!ovf) {
        for (int i = tid; i < neq; i += 1024) {
            if (eq_u[i] == uthr) {
                int s = atomicAdd(&s_cnte, 1);
                if (s < CAP_EX) eqex[s] = eq_i[i];
            }
        }
        __syncthreads();
        if (s_cnte <= CAP_EX) {
            if (tid == 0) {
                int cnt = s_cnte, last = -1;
                for (int r = 0; r < need_eq; r++) {
                    int best = 0x7fffffff;
                    for (int j = 0; j < cnt; j++) {
                        int v = eqex[j];
                        if (v > last && v < best) best = v;
                    }
                    sel_u[cnt_gt + r]   = uthr;
                    sel_idx[cnt_gt + r] = best;
                    last = best;
                }
            }
        } else {
            fell_back = true;
        }
        __syncthreads();
    }
    if (fell_back) {
        // register index-ordered fill via per-thread strided counts + scan.
        // Per-thread indices i = tid + p*1024 are increasing in p; global
        // index order across threads requires stable two-level ordering:
        // order by (i) == order by (p, tid). Count per thread, scan by
        // (p-major, tid-minor) ordering.
        int myeq = 0;
        #pragma unroll
        for (int p = 0; p < NPT_; p++) {
            int i = tid + p * 1024;
            if (i < TOT_ && uv[p] == uthr) myeq++;
        }
        eqcnt[tid] = myeq;
        __syncthreads();
        // For correct global-index order we need, for each hit (p,tid), the
        // number of hits with smaller global index i' = tid' + p'*1024 < i.
        // Rare path: do it serially on thread 0 over SMEM counts is wrong;
        // instead thread 0 rebuilds from gmem (correct + simple).
        if (tid == 0) {
            int p = 0;
            for (int i = 0; i < TOT_ && p < need_eq; i++) {
                if (mono(__ldg(base + i)) == uthr) {
                    sel_u[cnt_gt + p]   = uthr;
                    sel_idx[cnt_gt + p] = i;
                    p++;
                }
            }
        }
        __syncthreads();
    }
    __syncthreads();

    // ---- O(50^2) rank sort: (value desc, index asc) ----
    if (tid < TOPK_) {
        unsigned ui = sel_u[tid]; int ii = sel_idx[tid];
        int r = 0;
        for (int j = 0; j < TOPK_; j++) {
            unsigned uj = sel_u[j]; int ij = sel_idx[j];
            if (uj > ui || (uj == ui && ij < ii)) r++;
        }
        unsigned fb = (ui & 0x80000000u) ? (ui ^ 0x80000000u) : ~ui;
        fin_v[r] = __uint_as_float(fb);
        fin_i[r] = ii;
    }
    __syncthreads();

    // ---- epilogue: all small outputs ----
    if (tid < TOPK_) {
        int r   = tid;
        float val = fin_v[r];
        int   gi  = fin_i[r];
        int   q   = gi / C_;
        int   lab = gi - q * C_;
        g_topq[b * TOPK_ + r] = q;

        out[OFF_S + b * TOPK_ + r] = 1.0f / (1.0f + expf(-val));
        out[OFF_L + b * TOPK_ + r] = (float)lab;

        const float* bb = bbox + ((size_t)b * Q_ + q) * 4;
        float cx = bb[0], cy = bb[1], w = bb[2], h = bb[3];
        float ihh = (float)tsz[b * 2 + 0];
        float iww = (float)tsz[b * 2 + 1];
        float* ob = out + OFF_B + ((size_t)b * TOPK_ + r) * 4;
        ob[0] = (cx - 0.5f * w) * iww;
        ob[1] = (cy - 0.5f * h) * ihh;
        ob[2] = (cx + 0.5f * w) * iww;
        ob[3] = (cy + 0.5f * h) * ihh;

        const float* it = interms + ((size_t)b * Q_ + q) * C_;
        float m = it[0]; int am = 0;
        for (int c = 1; c < C_; c++) {
            float v = it[c];
            if (v > m) { m = v; am = c; }
        }
        out[OFF_SI + b * TOPK_ + r] = 1.0f / (1.0f + expf(-m));
        out[OFF_LI + b * TOPK_ + r] = (float)am;
    }
    if (tid == 0) {
        const float* ac = actions + (size_t)b * A_;
        float m = ac[0]; int am = 0;
        for (int a = 1; a < A_; a++)
            if (ac[a] > m) { m = ac[a]; am = a; }
        out[OFF_LA + b] = (float)am;
    }
}

// ---------------------------------------------------------------------------
// Masks kernel: one CTA per (b, rank) tile.
// Phase 1: sparse inverse-DCT with closed-form zigzag -> T[l][n] in SMEM.
// Phase 2: M[n][m] = sum_l T[l][n]*D[l][m], CONFLICT-FREE mapping:
//   warp w owns n rows [16w,16w+16); lane owns m cols [4*lane,4*lane+4).
//   Per l: D load = 1 LDS.128 at word 4*lane (banks swept, 0 conflicts),
//          T loads = 4 broadcast LDS.128. 5 LDS -> 64 FMA.
// ---------------------------------------------------------------------------
__global__ void __launch_bounds__(256, 2) masks_kernel(
    const float* __restrict__ vec, float* __restrict__ out)
{
    __shared__ float sD[LMAX_ * ML_];     // 11.75 KB
    __shared__ float sT[LMAX_ * ML_];     // 11.75 KB
    __shared__ float sv[NKEEP_];          // 1 KB
    __shared__ float red[17];

    int tid  = threadIdx.x;
    int tile = blockIdx.x;
    int b    = tile / TOPK_;
    int q    = g_topq[tile];

    sv[tid] = vec[((size_t)b * Q_ + q) * NKEEP_ + tid];
    {   // vectorized D load: 2944 floats = 736 float4
        const float4* src = reinterpret_cast<const float4*>(g_D);
        float4*       dst = reinterpret_cast<float4*>(sD);
        for (int i = tid; i < (LMAX_ * ML_) / 4; i += 256) dst[i] = src[i];
    }
    __syncthreads();

    // Phase 1: T[l][n], one coefficient per diagonal s >= l (s=22 only if l<=2)
    for (int idx = tid; idx < LMAX_ * ML_; idx += 256) {
        int l = idx >> 7, n = idx & 127;
        float acc = 0.0f;
        int smax = (l <= 2) ? 23 : 22;
        int tri  = (l * (l + 1)) >> 1;
        for (int s = l; s < smax; s++) {
            int t = (s & 1) ? (s - l) : l;
            acc = fmaf(sv[tri + t], sD[(s - l) * ML_ + n], acc);
            tri += s + 1;
        }
        sT[idx] = acc;
    }
    __syncthreads();

    // Phase 2: conflict-free register-blocked outer product
    int warp = tid >> 5;
    int lane = tid & 31;
    int n0   = warp << 4;       // 16 rows per warp
    int m0   = lane << 2;       // 4 cols per lane

    float acc[16][4];
    #pragma unroll
    for (int i = 0; i < 16; i++)
        #pragma unroll
        for (int j = 0; j < 4; j++) acc[i][j] = 0.0f;

    #pragma unroll 1
    for (int l = 0; l < LMAX_; l++) {
        float4 d  = *reinterpret_cast<const float4*>(&sD[l * ML_ + m0]);
        float4 t0 = *reinterpret_cast<const float4*>(&sT[l * ML_ + n0]);
        float4 t1 = *reinterpret_cast<const float4*>(&sT[l * ML_ + n0 + 4]);
        float4 t2 = *reinterpret_cast<const float4*>(&sT[l * ML_ + n0 + 8]);
        float4 t3 = *reinterpret_cast<const float4*>(&sT[l * ML_ + n0 + 12]);
        float tv[16] = {t0.x,t0.y,t0.z,t0.w, t1.x,t1.y,t1.z,t1.w,
                        t2.x,t2.y,t2.z,t2.w, t3.x,t3.y,t3.z,t3.w};
        #pragma unroll
        for (int i = 0; i < 16; i++) {
            acc[i][0] = fmaf(tv[i], d.x, acc[i][0]);
            acc[i][1] = fmaf(tv[i], d.y, acc[i][1]);
            acc[i][2] = fmaf(tv[i], d.z, acc[i][2]);
            acc[i][3] = fmaf(tv[i], d.w, acc[i][3]);
        }
    }

    // block max/min
    float mx = acc[0][0], mn = acc[0][0];
    #pragma unroll
    for (int i = 0; i < 16; i++)
        #pragma unroll
        for (int j = 0; j < 4; j++) {
            mx = fmaxf(mx, acc[i][j]); mn = fminf(mn, acc[i][j]);
        }
    for (int o = 16; o; o >>= 1) {
        mx = fmaxf(mx, __shfl_xor_sync(0xffffffffu, mx, o));
        mn = fminf(mn, __shfl_xor_sync(0xffffffffu, mn, o));
    }
    if (lane == 0) { red[warp] = mx; red[8 + warp] = mn; }
    __syncthreads();
    if (tid == 0) {
        float MX = red[0], MN = red[8];
        for (int w = 1; w < 8; w++) { MX = fmaxf(MX, red[w]); MN = fminf(MN, red[8 + w]); }
        red[16] = 0.5f * (MX + MN);
    }
    __syncthreads();
    float th = red[16];

    float* ob = out + OFF_M + (size_t)tile * (ML_ * ML_);
    #pragma unroll
    for (int i = 0; i < 16; i++) {
        float4 w4;
        w4.x = acc[i][0] > th ? 1.0f : 0.0f;
        w4.y = acc[i][1] > th ? 1.0f : 0.0f;
        w4.z = acc[i][2] > th ? 1.0f : 0.0f;
        w4.w = acc[i][3] > th ? 1.0f : 0.0f;
        *reinterpret_cast<float4*>(ob + (size_t)(n0 + i) * ML_ + m0) = w4;
    }
}

// ---------------------------------------------------------------------------
// Launch
// ---------------------------------------------------------------------------
extern "C" void kernel_launch(void* const* d_in, const int* in_sizes, int n_in,
                              void* d_out, int out_size)
{
    const float* logits  = (const float*)d_in[0];
    const float* bbox    = (const float*)d_in[1];
    const float* vec     = (const float*)d_in[2];
    const float* interms = (const float*)d_in[3];
    const float* actions = (const float*)d_in[4];
    const int*   tsz     = (const int*)d_in[5];
    float* out = (float*)d_out;

    topk_kernel<<<B_, 1024>>>(logits, bbox, interms, actions, tsz, out);
    masks_kernel<<<B_ * TOPK_, 256>>>(vec, out);
}